// round 1
// baseline (speedup 1.0000x reference)
#include <cuda_runtime.h>
#include <cstdint>

#define BB 512
#define TT 4096
#define SS 64
#define MM 125

// obs[b][t] in [0,125) — scratch via __device__ global (no allocations allowed)
__device__ __align__(16) unsigned char g_obs[BB * TT];

// ---------------------------------------------------------------------------
// Kernel 1: decode one-hot rows -> obs indices. One warp per (b,t) row.
// Early-exit after the 32-float chunk containing the 1.0 (saves ~40% DRAM).
// ---------------------------------------------------------------------------
__global__ void __launch_bounds__(256) decode_kernel(const float* __restrict__ x) {
    int gwarp = (blockIdx.x * 256 + threadIdx.x) >> 5;
    int lane = threadIdx.x & 31;
    if (gwarp >= BB * TT) return;
    const float* row = x + (long long)gwarp * MM;
    int found = 0;
#pragma unroll
    for (int c = 0; c < 4; c++) {
        int idx = c * 32 + lane;
        float v = (idx < MM) ? __ldcs(row + idx) : 0.0f;
        unsigned m = __ballot_sync(0xffffffffu, v > 0.5f);
        if (m) { found = c * 32 + (__ffs(m) - 1); break; }
    }
    if (lane == 0) g_obs[gwarp] = (unsigned char)found;
}

// packed f32x2 FMA — only reachable via PTX (ptxas never auto-fuses)
__device__ __forceinline__ void ffma2(float2& d, float2 a, float2 b, float2 c) {
    asm("fma.rn.f32x2 %0, %1, %2, %3;"
        : "=l"(*(unsigned long long*)&d)
        : "l"(*(unsigned long long*)&a),
          "l"(*(unsigned long long*)&b),
          "l"(*(unsigned long long*)&c));
}

// ---------------------------------------------------------------------------
// Kernel 2: HMM forward scan. One warp per batch chain.
// lane j owns states {j, j+32}; A columns k-pair-packed in registers.
// alpha ping-pongs through shared; renormalize every 8 steps (telescoping).
// ---------------------------------------------------------------------------
__global__ void __launch_bounds__(128) scan_kernel(
    const float* __restrict__ Ivec,
    const float* __restrict__ A,
    const float* __restrict__ Bm,
    float* __restrict__ out)
{
    __shared__ float sB[MM * SS];                  // 32000 B, emission rows
    __shared__ float sAlpha[4][2][SS];             // per-warp double buffer
    __shared__ __align__(16) unsigned char sObs[4][512];

    const int tid = threadIdx.x;
    const int w = tid >> 5;
    const int lane = tid & 31;
    const int b = blockIdx.x * 4 + w;

    // stage Bm into shared (flat copy: layout already matches)
    for (int i = tid; i < (MM * SS) / 4; i += 128)
        ((float4*)sB)[i] = ((const float4*)Bm)[i];
    __syncthreads();

    // A column k-pairs in registers (loop-invariant):
    // aA[kp] = (A[2kp][lane],    A[2kp+1][lane])     for state s0 = lane
    // aB[kp] = (A[2kp][lane+32], A[2kp+1][lane+32])  for state s1 = lane+32
    float2 aA[32], aB[32];
#pragma unroll
    for (int kp = 0; kp < 32; kp++) {
        aA[kp].x = A[(2 * kp)     * SS + lane];
        aA[kp].y = A[(2 * kp + 1) * SS + lane];
        aB[kp].x = A[(2 * kp)     * SS + lane + 32];
        aB[kp].y = A[(2 * kp + 1) * SS + lane + 32];
    }

    const float i0 = Ivec[lane];
    const float i1 = Ivec[lane + 32];

    const unsigned char* gob = g_obs + b * TT;

    // stage first 512 obs bytes
    ((int4*)sObs[w])[lane] = ((const int4*)gob)[lane];
    __syncwarp();

    // t = 0: u = E0 * I   (unnormalized; folds into first block's Z)
    int ob = sObs[w][0];
    float u0 = sB[ob * SS + lane]      * i0;
    float u1 = sB[ob * SS + 32 + lane] * i1;
    sAlpha[w][0][lane]      = u0;
    sAlpha[w][0][lane + 32] = u1;
    float ll = 0.0f;
    __syncwarp();

    for (int t = 1; t < TT; t++) {
        if ((t & 511) == 0) {
            ((int4*)sObs[w])[lane] = ((const int4*)(gob + t))[lane];
            __syncwarp();
        }
        const int rb = (t - 1) & 1;
        const int wb = t & 1;

        ob = sObs[w][t & 511];
        float e0 = sB[ob * SS + lane];
        float e1 = sB[ob * SS + 32 + lane];

        // R[s] = sum_k alpha[k] * A[k][s]   (64 FFMA2, 4 acc chains)
        const float4* ap = (const float4*)sAlpha[w][rb];
        float2 accA0 = {0.f, 0.f}, accA1 = {0.f, 0.f};
        float2 accB0 = {0.f, 0.f}, accB1 = {0.f, 0.f};
#pragma unroll
        for (int q = 0; q < 16; q++) {
            float4 al = ap[q];                 // alpha[4q .. 4q+3] (broadcast)
            float2 alo = make_float2(al.x, al.y);
            float2 ahi = make_float2(al.z, al.w);
            ffma2(accA0, alo, aA[2 * q],     accA0);
            ffma2(accA1, ahi, aA[2 * q + 1], accA1);
            ffma2(accB0, alo, aB[2 * q],     accB0);
            ffma2(accB1, ahi, aB[2 * q + 1], accB1);
        }
        float r0 = (accA0.x + accA0.y) + (accA1.x + accA1.y);
        float r1 = (accB0.x + accB0.y) + (accB1.x + accB1.y);
        u0 = e0 * r0;
        u1 = e1 * r1;

        // renormalize every 8 steps (covers t=4095: 4095&7 == 7)
        if ((t & 7) == 7) {
            float s = u0 + u1;
#pragma unroll
            for (int o = 16; o; o >>= 1) s += __shfl_xor_sync(0xffffffffu, s, o);
            ll += __logf(s);
            float inv = __fdividef(1.0f, s);
            u0 *= inv;
            u1 *= inv;
        }

        sAlpha[w][wb][lane]      = u0;
        sAlpha[w][wb][lane + 32] = u1;
        __syncwarp();
    }

    if (lane == 0) out[b] = ll;
}

extern "C" void kernel_launch(void* const* d_in, const int* in_sizes, int n_in,
                              void* d_out, int out_size) {
    const float* x  = (const float*)d_in[0];   // [512, 4096, 125]
    const float* I  = (const float*)d_in[1];   // [1, 64]
    const float* A  = (const float*)d_in[2];   // [64, 64]
    const float* Bm = (const float*)d_in[3];   // [125, 64]
    float* out = (float*)d_out;                // [512, 1]

    const int rows = BB * TT;                  // 2,097,152 rows, warp per row
    decode_kernel<<<(rows * 32) / 256, 256>>>(x);
    scan_kernel<<<BB / 4, 128>>>(I, A, Bm, out);
}